// round 2
// baseline (speedup 1.0000x reference)
#include <cuda_runtime.h>

#define N_NODES   50000
#define EMB       320
#define HID       64
#define NH        128          // two 64-wide halves of P
#define N_EDGES   400000

// Scratch (no allocations allowed): P = embed @ [W1a | W1b]  (25.6 MB), cvec, dtype flag
__device__ float g_P[N_NODES * NH];
__device__ float g_cvec[HID];
__device__ int   g_idx64;

// ---------------------------------------------------------------------------
// Kernel 0: detect edge_index element width.
// int64 data viewed as int32 words -> odd words (high halves) are all 0.
// int32 data -> odd words are random node ids (all-zero prob ~ (1/50000)^32).
// ---------------------------------------------------------------------------
__global__ void detect_kernel(const int* __restrict__ ei_raw) {
    int is64 = 1;
    #pragma unroll
    for (int i = 0; i < 32; i++)
        if (ei_raw[2 * i + 1] != 0) { is64 = 0; break; }
    g_idx64 = is64;
}

// ---------------------------------------------------------------------------
// Kernel 1: P[v, 0:64]  = embed[v] @ W1[0:320, :]
//           P[v,64:128] = embed[v] @ W1[320:640, :]
// Tiled SGEMM: M=50000, N=128, K=320. Block = 256 thr, tile 64x128,
// micro-tile 8x4 per thread, BK=16.
// ---------------------------------------------------------------------------
__global__ __launch_bounds__(256) void gemm_kernel(const float* __restrict__ embed,
                                                   const float* __restrict__ W1) {
    __shared__ float As[16][64];    // [k][m]
    __shared__ float Bs[16][128];   // [k][j]

    const int m0  = blockIdx.x * 64;
    const int tid = threadIdx.x;
    const int tr  = tid >> 5;   // 0..7  (row group)
    const int tc  = tid & 31;   // 0..31 (col group, 4 cols each)

    float acc[8][4];
    #pragma unroll
    for (int i = 0; i < 8; i++)
        #pragma unroll
        for (int j = 0; j < 4; j++) acc[i][j] = 0.f;

    for (int k0 = 0; k0 < EMB; k0 += 16) {
        // --- load A tile: 64 rows x 16 k (float4 per thread) ---
        {
            int r  = tid >> 2;   // 0..63
            int c4 = tid & 3;    // which float4 of the 16-k strip
            int gm = m0 + r;
            float4 v = make_float4(0.f, 0.f, 0.f, 0.f);
            if (gm < N_NODES)
                v = *reinterpret_cast<const float4*>(&embed[(size_t)gm * EMB + k0 + c4 * 4]);
            As[c4 * 4 + 0][r] = v.x;
            As[c4 * 4 + 1][r] = v.y;
            As[c4 * 4 + 2][r] = v.z;
            As[c4 * 4 + 3][r] = v.w;
        }
        // --- load B tile: 16 k x 128 j, gathered from the two W1 blocks ---
        #pragma unroll
        for (int r = 0; r < 8; r++) {
            int idx = tid + 256 * r;
            int kk  = idx >> 7;      // 0..15
            int j   = idx & 127;     // 0..127
            float v = (j < 64) ? W1[(k0 + kk) * 64 + j]
                               : W1[(320 + k0 + kk) * 64 + (j - 64)];
            Bs[kk][j] = v;
        }
        __syncthreads();

        #pragma unroll
        for (int k = 0; k < 16; k++) {
            float4 a0 = *reinterpret_cast<const float4*>(&As[k][tr * 8]);
            float4 a1 = *reinterpret_cast<const float4*>(&As[k][tr * 8 + 4]);
            float4 b  = *reinterpret_cast<const float4*>(&Bs[k][tc * 4]);
            float am[8] = {a0.x, a0.y, a0.z, a0.w, a1.x, a1.y, a1.z, a1.w};
            float bn[4] = {b.x, b.y, b.z, b.w};
            #pragma unroll
            for (int i = 0; i < 8; i++)
                #pragma unroll
                for (int j = 0; j < 4; j++)
                    acc[i][j] = fmaf(am[i], bn[j], acc[i][j]);
        }
        __syncthreads();
    }

    #pragma unroll
    for (int i = 0; i < 8; i++) {
        int gm = m0 + tr * 8 + i;
        if (gm < N_NODES) {
            float4 v = make_float4(acc[i][0], acc[i][1], acc[i][2], acc[i][3]);
            *reinterpret_cast<float4*>(&g_P[(size_t)gm * NH + tc * 4]) = v;
        }
    }
}

// ---------------------------------------------------------------------------
// Kernel 2: cvec[j] = b1[j] + embed[node_id] @ W1[640:960, j]
// ---------------------------------------------------------------------------
__global__ void cvec_kernel(const float* __restrict__ embed,
                            const float* __restrict__ W1,
                            const float* __restrict__ b1,
                            const int*   __restrict__ nid) {
    int j = threadIdx.x;                 // 0..63
    int n = nid[0];                      // low 32 bits (little-endian: ok for i32/i64)
    const float* er = &embed[(size_t)n * EMB];
    float s = b1[j];
    #pragma unroll 4
    for (int k = 0; k < EMB; k++)
        s = fmaf(er[k], W1[(640 + k) * 64 + j], s);
    g_cvec[j] = s;
}

// ---------------------------------------------------------------------------
// Kernel 3: per-edge: h = relu(P[col][0:64] + P[row][64:128] + cvec)
//           w = h . W2 + b2 ; concrete gate -> sigmoid
// One warp per edge; lane i handles h[i] and h[i+32].
// ---------------------------------------------------------------------------
__global__ __launch_bounds__(256) void edge_kernel(const void* __restrict__ ei_raw,
                                                   const float* __restrict__ eps,
                                                   const float* __restrict__ W2,
                                                   const float* __restrict__ b2,
                                                   const float* __restrict__ tmp,
                                                   float* __restrict__ out) {
    int warp = (blockIdx.x * blockDim.x + threadIdx.x) >> 5;
    int lane = threadIdx.x & 31;
    if (warp >= N_EDGES) return;

    int col, row;
    if (g_idx64) {
        const long long* e64 = (const long long*)ei_raw;
        col = (int)e64[warp];
        row = (int)e64[N_EDGES + warp];
    } else {
        const int* e32 = (const int*)ei_raw;
        col = e32[warp];
        row = e32[N_EDGES + warp];
    }

    const float* Pc = &g_P[(size_t)col * NH];        // first half  (col @ W1a)
    const float* Pr = &g_P[(size_t)row * NH + 64];   // second half (row @ W1b)

    float h1 = Pc[lane]      + Pr[lane]      + g_cvec[lane];
    float h2 = Pc[lane + 32] + Pr[lane + 32] + g_cvec[lane + 32];
    h1 = fmaxf(h1, 0.f);
    h2 = fmaxf(h2, 0.f);

    float p = fmaf(h1, W2[lane], h2 * W2[lane + 32]);
    #pragma unroll
    for (int o = 16; o > 0; o >>= 1)
        p += __shfl_xor_sync(0xffffffffu, p, o);

    if (lane == 0) {
        float w    = p + b2[0];
        const float bias = 0.0001f;
        float e    = eps[warp] * (1.f - 2.f * bias) + bias;
        float gate = (logf(e) - log1pf(-e) + w) / tmp[0];
        out[warp]  = 1.f / (1.f + expf(-gate));
    }
}

// ---------------------------------------------------------------------------
// Inputs (metadata order): 0:x 1:embed 2:edge_index 3:node_id 4:tmp 5:eps
//                          6:W1 7:b1 8:W2 9:b2
// ---------------------------------------------------------------------------
extern "C" void kernel_launch(void* const* d_in, const int* in_sizes, int n_in,
                              void* d_out, int out_size) {
    const float* embed = (const float*)d_in[1];
    const void*  ei    = d_in[2];
    const int*   nid   = (const int*)d_in[3];
    const float* tmp   = (const float*)d_in[4];
    const float* eps   = (const float*)d_in[5];
    const float* W1    = (const float*)d_in[6];
    const float* b1    = (const float*)d_in[7];
    const float* W2    = (const float*)d_in[8];
    const float* b2    = (const float*)d_in[9];
    float* out = (float*)d_out;

    detect_kernel<<<1, 1>>>((const int*)ei);
    gemm_kernel<<<(N_NODES + 63) / 64, 256>>>(embed, W1);
    cvec_kernel<<<1, 64>>>(embed, W1, b1, nid);
    edge_kernel<<<(N_EDGES * 32 + 255) / 256, 256>>>(ei, eps, W2, b2, tmp, out);
}